// round 15
// baseline (speedup 1.0000x reference)
#include <cuda_runtime.h>

// PlanarQuantMSE — TMA bulk-store variant.
// Compute identical to R14 (byte-LUT quantizer, exact boundary). Outputs are
// staged to smem with STS.128 (cheap LSU issue) and written to gmem by the
// TMA engine via two 16KB cp.async.bulk (shared->global) per CTA, removing
// ~2/3 of the store cost from the LSU pipe. Issuing thread waits bulk-group 0
// before exit (data guaranteed in gmem at kernel end).
// Output: [x_hat | indices-as-float] concatenated.

#define ROWS 4096
#define DIM  4096
#define TPB  256
#define VPT  4        // float4s per thread (TPB*4*VPT == DIM)
#define NCELL 1024
#define SCALEF 455.0f
// magic = 2^23*1.5 + 512 ; cell = bits(fma(v,S,magic)) - 0x4B400000 = round(v*S)+512
// |r| <= 1+3e-7 => cell in [57, 968]: no clamp needed.
#define MAGICF 12583424.0f
#define BITBASE 0x4B400000

__global__ __launch_bounds__(TPB, 6)
void pq_kernel(const float* __restrict__ x,
               const float* __restrict__ cent,
               const float* __restrict__ rot2,
               float* __restrict__ xhat,
               float* __restrict__ idxout)
{
    __shared__ float  xs[DIM];                // 16 KB x_hat staging
    __shared__ float  is_[DIM];               // 16 KB indices staging
    __shared__ unsigned char lut_sh[NCELL];
    __shared__ float  mid_sh[16];
    __shared__ float  c_sh[16];
    __shared__ int    tc_sh[15];
    __shared__ float  red[TPB / 32];
    __shared__ float  norm_sh;
    __shared__ int    flag_sh;

    const int row = blockIdx.x;
    const int t   = threadIdx.x;

    // ---- issue x loads first so DRAM streams while we do table setup ----
    const float4* xr = (const float4*)(x + (size_t)row * DIM);
    float4 v[VPT];
#pragma unroll
    for (int k = 0; k < VPT; k++) v[k] = __ldcs(&xr[t + k * TPB]);

    // ---- warp-0 setup: centroids, midpoints, cell ids, dup flag ----
    if (t < 16) {
        float cv = __ldg(&cent[t]);
        c_sh[t] = cv;
        float cn = __shfl_down_sync(0x0000ffffu, cv, 1);
        float mm = 0.5f * (cv + cn);
        int cell = __float_as_int(fmaf(mm, SCALEF, MAGICF)) - BITBASE;
        if (t < 15) { mid_sh[t] = mm; tc_sh[t] = cell; }
        else        { mid_sh[15] = 3.0e38f; }
        int celln = __shfl_down_sync(0x0000ffffu, cell, 1);
        unsigned dup = __ballot_sync(0x0000ffffu, (t < 14) && (cell == celln));
        if (t == 0) flag_sh = (dup != 0u) ? 1 : 0;
    }

    // ---- row sum of squares ----
    float ss = 0.0f;
#pragma unroll
    for (int k = 0; k < VPT; k++)
        ss += v[k].x * v[k].x + v[k].y * v[k].y
            + v[k].z * v[k].z + v[k].w * v[k].w;
#pragma unroll
    for (int o = 16; o > 0; o >>= 1)
        ss += __shfl_xor_sync(0xffffffffu, ss, o);
    if ((t & 31) == 0) red[t >> 5] = ss;
    __syncthreads();                                   // barrier A

    // ---- byte-LUT build: 4 cells/thread, one packed STS.32 ----
    {
        const int base = t * 4;
        int L0 = 0, L1 = 0, L2 = 0, L3 = 0;
#pragma unroll
        for (int j = 0; j < 15; j++) {
            int cj = tc_sh[j];
            L0 += (cj < base)     ? 1 : 0;
            L1 += (cj < base + 1) ? 1 : 0;
            L2 += (cj < base + 2) ? 1 : 0;
            L3 += (cj < base + 3) ? 1 : 0;
        }
        ((unsigned int*)lut_sh)[t] =
            (unsigned)L0 | ((unsigned)L1 << 8) | ((unsigned)L2 << 16) | ((unsigned)L3 << 24);
    }

    if (t < (TPB / 32)) {
        float s2 = red[t];
#pragma unroll
        for (int o = (TPB / 64); o > 0; o >>= 1)
            s2 += __shfl_xor_sync((1u << (TPB / 32)) - 1u, s2, o);
        if (t == 0) norm_sh = fmaxf(sqrtf(s2), 1e-8f);
    }
    __syncthreads();                                   // barrier B

    const float norm = norm_sh;
    const float inv  = 1.0f / norm;
    const int   flag = flag_sh;

    const float4* rr = (const float4*)rot2;            // (c,s,c,s) per float4
    float4* xo = (float4*)xs;                          // smem staging
    float4* io = (float4*)is_;

#pragma unroll
    for (int k = 0; k < VPT; k++) {
        const int j = t + k * TPB;
        const float4 rs = __ldg(&rr[j]);

        const float v0 = v[k].x * inv, v1 = v[k].y * inv;
        const float v2 = v[k].z * inv, v3 = v[k].w * inv;

        float r[4];
        r[0] = rs.x * v0 - rs.y * v1;
        r[1] = rs.y * v0 + rs.x * v1;
        r[2] = rs.z * v2 - rs.w * v3;
        r[3] = rs.w * v2 + rs.z * v3;

        float q[4], f[4];
        if (!flag) {
#pragma unroll
            for (int e = 0; e < 4; e++) {
                int cell = __float_as_int(fmaf(r[e], SCALEF, MAGICF)) - BITBASE;
                int L    = (int)lut_sh[cell];                 // narrow byte LDS
                int idx  = L + ((r[e] > mid_sh[L]) ? 1 : 0);  // bcast + exact cmp
                q[e] = c_sh[idx];                             // bcast
                f[e] = (float)idx;
            }
        } else {
#pragma unroll
            for (int e = 0; e < 4; e++) {
                int idx = 0;
#pragma unroll
                for (int jj = 0; jj < 15; jj++) idx += (r[e] > mid_sh[jj]) ? 1 : 0;
                q[e] = c_sh[idx];
                f[e] = (float)idx;
            }
        }

        float4 out;
        out.x = (rs.x * q[0] + rs.y * q[1]) * norm;
        out.y = (rs.x * q[1] - rs.y * q[0]) * norm;
        out.z = (rs.z * q[2] + rs.w * q[3]) * norm;
        out.w = (rs.z * q[3] - rs.w * q[2]) * norm;
        xo[j] = out;                                   // STS.128 (cheap)

        float4 fo;
        fo.x = f[0]; fo.y = f[1]; fo.z = f[2]; fo.w = f[3];
        io[j] = fo;                                    // STS.128 (cheap)
    }

    __syncthreads();                                   // staging complete

    if (t == 0) {
        asm volatile("fence.proxy.async.shared::cta;" ::: "memory");
        unsigned sx = (unsigned)__cvta_generic_to_shared(xs);
        unsigned si = (unsigned)__cvta_generic_to_shared(is_);
        float* gx = xhat   + (size_t)row * DIM;
        float* gi = idxout + (size_t)row * DIM;
        asm volatile("cp.async.bulk.global.shared::cta.bulk_group [%0], [%1], %2;"
                     :: "l"(gx), "r"(sx), "n"(DIM * 4) : "memory");
        asm volatile("cp.async.bulk.global.shared::cta.bulk_group [%0], [%1], %2;"
                     :: "l"(gi), "r"(si), "n"(DIM * 4) : "memory");
        asm volatile("cp.async.bulk.commit_group;" ::: "memory");
        asm volatile("cp.async.bulk.wait_group 0;" ::: "memory");
    }
}

extern "C" void kernel_launch(void* const* d_in, const int* in_sizes, int n_in,
                              void* d_out, int out_size) {
    const float* x = nullptr;
    const float* cent = nullptr;
    const float* rot2 = nullptr;
    for (int i = 0; i < n_in; i++) {
        if (in_sizes[i] == ROWS * DIM) x    = (const float*)d_in[i];
        else if (in_sizes[i] == 16)    cent = (const float*)d_in[i];
        else if (in_sizes[i] == 4096)  rot2 = (const float*)d_in[i];
    }

    float* xhat = (float*)d_out;
    float* idxf = xhat + (long long)ROWS * DIM;

    pq_kernel<<<ROWS, TPB>>>(x, cent, rot2, xhat, idxf);
}

// round 16
// speedup vs baseline: 1.1482x; 1.1482x over previous
#include <cuda_runtime.h>

// PlanarQuantMSE — two rows per CTA (TPB=512, grid=2048).
// Same proven byte-LUT quantizer + exact boundary as R10; each CTA processes
// rows {2b, 2b+1} with 2 float4/thread/row (16 data regs, same as R10), so
// every barrier covers 32KB of work and table setup amortizes over 2 rows.
// Two independent norm reductions interleave for extra ILP around barriers.
// Output: [x_hat | indices-as-float] concatenated.

#define ROWS 4096
#define DIM  4096
#define TPB  512
#define VPT  2        // float4s per thread PER ROW (TPB*4*VPT == DIM)
#define NWARP (TPB / 32)
#define NCELL 1024
#define SCALEF 455.0f
// magic = 2^23*1.5 + 512 ; cell = bits(fma(v,S,magic)) - 0x4B400000 = round(v*S)+512
// |r| <= 1+3e-7 => cell in [57, 968]: no clamp needed.
#define MAGICF 12583424.0f
#define BITBASE 0x4B400000

__global__ __launch_bounds__(TPB, 3)
void pq_kernel(const float* __restrict__ x,
               const float* __restrict__ cent,
               const float* __restrict__ rot2,
               float* __restrict__ xhat,
               float* __restrict__ idxout)
{
    __shared__ unsigned char lut_sh[NCELL];
    __shared__ float  mid_sh[16];
    __shared__ float  c_sh[16];
    __shared__ int    tc_sh[15];
    __shared__ float  red[2][NWARP];
    __shared__ int    flag_sh;

    const int row0 = blockIdx.x * 2;
    const int t    = threadIdx.x;
    const int w    = t >> 5;

    // ---- issue both rows' loads first (DRAM streams during setup) ----
    const float4* xr0 = (const float4*)(x + (size_t)row0 * DIM);
    const float4* xr1 = (const float4*)(x + (size_t)(row0 + 1) * DIM);
    float4 v0[VPT], v1[VPT];
#pragma unroll
    for (int k = 0; k < VPT; k++) v0[k] = xr0[t + k * TPB];
#pragma unroll
    for (int k = 0; k < VPT; k++) v1[k] = xr1[t + k * TPB];

    // ---- warp-0 setup: centroids, midpoints, cell ids, dup flag ----
    if (t < 16) {
        float cv = __ldg(&cent[t]);
        c_sh[t] = cv;
        float cn = __shfl_down_sync(0x0000ffffu, cv, 1);
        float mm = 0.5f * (cv + cn);
        int cell = __float_as_int(fmaf(mm, SCALEF, MAGICF)) - BITBASE;
        if (t < 15) { mid_sh[t] = mm; tc_sh[t] = cell; }
        else        { mid_sh[15] = 3.0e38f; }
        int celln = __shfl_down_sync(0x0000ffffu, cell, 1);
        unsigned dup = __ballot_sync(0x0000ffffu, (t < 14) && (cell == celln));
        if (t == 0) flag_sh = (dup != 0u) ? 1 : 0;
    }

    // ---- both rows' sums of squares (interleaved shuffles = ILP) ----
    float ss0 = 0.0f, ss1 = 0.0f;
#pragma unroll
    for (int k = 0; k < VPT; k++) {
        ss0 += v0[k].x * v0[k].x + v0[k].y * v0[k].y
             + v0[k].z * v0[k].z + v0[k].w * v0[k].w;
        ss1 += v1[k].x * v1[k].x + v1[k].y * v1[k].y
             + v1[k].z * v1[k].z + v1[k].w * v1[k].w;
    }
#pragma unroll
    for (int o = 16; o > 0; o >>= 1) {
        ss0 += __shfl_xor_sync(0xffffffffu, ss0, o);
        ss1 += __shfl_xor_sync(0xffffffffu, ss1, o);
    }
    if ((t & 31) == 0) { red[0][w] = ss0; red[1][w] = ss1; }
    __syncthreads();                                   // barrier A

    // ---- byte-LUT build: threads 0..255, 4 cells each, packed STS.32 ----
    if (t < NCELL / 4) {
        const int base = t * 4;
        int L0 = 0, L1 = 0, L2 = 0, L3 = 0;
#pragma unroll
        for (int j = 0; j < 15; j++) {
            int cj = tc_sh[j];
            L0 += (cj < base)     ? 1 : 0;
            L1 += (cj < base + 1) ? 1 : 0;
            L2 += (cj < base + 2) ? 1 : 0;
            L3 += (cj < base + 3) ? 1 : 0;
        }
        ((unsigned int*)lut_sh)[t] =
            (unsigned)L0 | ((unsigned)L1 << 8) | ((unsigned)L2 << 16) | ((unsigned)L3 << 24);
    }
    __syncthreads();                                   // barrier B

    // per-thread norm finish from the 16 partials (broadcast LDS)
    float s20 = 0.0f, s21 = 0.0f;
#pragma unroll
    for (int p = 0; p < NWARP; p++) { s20 += red[0][p]; s21 += red[1][p]; }
    const float norm0 = fmaxf(sqrtf(s20), 1e-8f);
    const float inv0  = 1.0f / norm0;
    const float norm1 = fmaxf(sqrtf(s21), 1e-8f);
    const float inv1  = 1.0f / norm1;
    const int   flag  = flag_sh;

    const float4* rr = (const float4*)rot2;            // (c,s,c,s) per float4

#pragma unroll
    for (int rowi = 0; rowi < 2; rowi++) {
        const float norm = rowi ? norm1 : norm0;
        const float inv  = rowi ? inv1  : inv0;
        const int   row  = row0 + rowi;
        float4* xo = (float4*)(xhat   + (size_t)row * DIM);
        float4* io = (float4*)(idxout + (size_t)row * DIM);

#pragma unroll
        for (int k = 0; k < VPT; k++) {
            const int j = t + k * TPB;
            const float4 rs = __ldg(&rr[j]);           // L1-hit after first use
            const float4 xv = rowi ? v1[k] : v0[k];

            const float a0 = xv.x * inv, a1 = xv.y * inv;
            const float a2 = xv.z * inv, a3 = xv.w * inv;

            float r[4];
            r[0] = rs.x * a0 - rs.y * a1;
            r[1] = rs.y * a0 + rs.x * a1;
            r[2] = rs.z * a2 - rs.w * a3;
            r[3] = rs.w * a2 + rs.z * a3;

            float q[4], f[4];
            if (!flag) {
#pragma unroll
                for (int e = 0; e < 4; e++) {
                    int cell = __float_as_int(fmaf(r[e], SCALEF, MAGICF)) - BITBASE;
                    int L    = (int)lut_sh[cell];                 // narrow byte LDS
                    int idx  = L + ((r[e] > mid_sh[L]) ? 1 : 0);  // bcast + exact cmp
                    q[e] = c_sh[idx];                             // bcast
                    f[e] = (float)idx;
                }
            } else {
#pragma unroll
                for (int e = 0; e < 4; e++) {
                    int idx = 0;
#pragma unroll
                    for (int jj = 0; jj < 15; jj++) idx += (r[e] > mid_sh[jj]) ? 1 : 0;
                    q[e] = c_sh[idx];
                    f[e] = (float)idx;
                }
            }

            float4 out;
            out.x = (rs.x * q[0] + rs.y * q[1]) * norm;
            out.y = (rs.x * q[1] - rs.y * q[0]) * norm;
            out.z = (rs.z * q[2] + rs.w * q[3]) * norm;
            out.w = (rs.z * q[3] - rs.w * q[2]) * norm;
            xo[j] = out;

            float4 fo;
            fo.x = f[0]; fo.y = f[1]; fo.z = f[2]; fo.w = f[3];
            io[j] = fo;
        }
    }
}

extern "C" void kernel_launch(void* const* d_in, const int* in_sizes, int n_in,
                              void* d_out, int out_size) {
    const float* x = nullptr;
    const float* cent = nullptr;
    const float* rot2 = nullptr;
    for (int i = 0; i < n_in; i++) {
        if (in_sizes[i] == ROWS * DIM) x    = (const float*)d_in[i];
        else if (in_sizes[i] == 16)    cent = (const float*)d_in[i];
        else if (in_sizes[i] == 4096)  rot2 = (const float*)d_in[i];
    }

    float* xhat = (float*)d_out;
    float* idxf = xhat + (long long)ROWS * DIM;

    pq_kernel<<<ROWS / 2, TPB>>>(x, cent, rot2, xhat, idxf);
}